// round 4
// baseline (speedup 1.0000x reference)
#include <cuda_runtime.h>
#include <cuda_bf16.h>

#define NN 100000
#define NE 1250000
#define DD 64
#define K_ITERS 5
#define EPSF 1e-8f
#define NB_NODE 391            // ceil(NN/256)

// Scratch (device globals — allocation-free). All state rewritten every call.
__device__ __align__(16) float g_hn[NN * DD]; // normalized tanh features
__device__ float g_deg[NN];     // weighted degree (incl. self loop)
__device__ float g_dis[NN];     // deg^{-1/2}
__device__ float g_f[NN];       // propagation ping
__device__ float g_f2[NN];      // propagation pong
__device__ float g_f0[NN];      // relu(mask)
// CSR by destination
__device__ int   g_cnt[NN];     // in-degree counts
__device__ int   g_off[NN];     // exclusive-scan offsets
__device__ int   g_cur[NN];     // scatter cursors
__device__ int   g_part[512];   // block partial sums (NB_NODE used)
__device__ int   g_csrc[NE];    // CSR: source node per slot
__device__ float g_cw[NE];      // CSR: normalized weight per slot

// ---------------------------------------------------------------------------
// K1: h = tanh(x @ W^T + b), normalized rows: hn = h / max(||h||, eps)
// ---------------------------------------------------------------------------
__global__ void k_feat(const float* __restrict__ x, const float* __restrict__ W,
                       const float* __restrict__ b) {
    __shared__ float xs[8][DD];
    int warp = threadIdx.x >> 5;
    int lane = threadIdx.x & 31;
    int n = blockIdx.x * 8 + warp;
    if (n >= NN) return;

    xs[warp][lane]      = x[n * DD + lane];
    xs[warp][lane + 32] = x[n * DD + lane + 32];
    __syncwarp();

    float acc0 = b[lane];
    float acc1 = b[lane + 32];
    const float* w0 = W + lane * DD;
    const float* w1 = W + (lane + 32) * DD;
#pragma unroll
    for (int k = 0; k < DD; k++) {
        float xv = xs[warp][k];
        acc0 = fmaf(xv, w0[k], acc0);
        acc1 = fmaf(xv, w1[k], acc1);
    }
    acc0 = tanhf(acc0);
    acc1 = tanhf(acc1);

    float ss = acc0 * acc0 + acc1 * acc1;
#pragma unroll
    for (int o = 16; o; o >>= 1) ss += __shfl_xor_sync(0xffffffffu, ss, o);
    float inv = 1.0f / fmaxf(sqrtf(ss), EPSF);

    g_hn[n * DD + lane]      = acc0 * inv;
    g_hn[n * DD + lane + 32] = acc1 * inv;
}

// ---------------------------------------------------------------------------
// K_init: deg = 1 (self loop), cnt = 0, f0 = relu(mask), f = f0
// ---------------------------------------------------------------------------
__global__ void k_init(const float* __restrict__ mask) {
    int n = blockIdx.x * blockDim.x + threadIdx.x;
    if (n < NN) {
        g_deg[n] = 1.0f;
        g_cnt[n] = 0;
        float f0 = fmaxf(mask[n], 0.0f);
        g_f0[n] = f0;
        g_f[n]  = f0;
    }
}

// ---------------------------------------------------------------------------
// K2: edge cosine (relu), weighted-degree + in-degree-count accumulation.
// 16 lanes per edge, float4. edge_index is int32.
// ---------------------------------------------------------------------------
__global__ void k_edge(const int* __restrict__ ei, float* __restrict__ ew_out) {
    int t = blockIdx.x * blockDim.x + threadIdx.x;
    int e = t >> 4;
    int sub = t & 15;
    if (e >= NE) return;

    int s = ei[e];
    int d = ei[NE + e];

    float4 a = *(const float4*)(g_hn + s * DD + sub * 4);
    float4 c = *(const float4*)(g_hn + d * DD + sub * 4);
    float p = a.x * c.x + a.y * c.y + a.z * c.z + a.w * c.w;
#pragma unroll
    for (int o = 8; o; o >>= 1) p += __shfl_xor_sync(0xffffffffu, p, o);

    if (sub == 0) {
        float w = fmaxf(p, 0.0f);
        ew_out[e] = w;
        atomicAdd(&g_deg[d], w);
        atomicAdd(&g_cnt[d], 1);
    }
}

// ---------------------------------------------------------------------------
// K3: dis = rsqrt(max(deg, eps))
// ---------------------------------------------------------------------------
__global__ void k_dis() {
    int n = blockIdx.x * blockDim.x + threadIdx.x;
    if (n < NN) g_dis[n] = rsqrtf(fmaxf(g_deg[n], EPSF));
}

// ---------------------------------------------------------------------------
// CSR build: block sums -> inclusive scan of partials -> local scan + base.
// ---------------------------------------------------------------------------
__global__ void k_blocksum() {
    __shared__ int sh[256];
    int t = threadIdx.x;
    int n = blockIdx.x * 256 + t;
    sh[t] = (n < NN) ? g_cnt[n] : 0;
    __syncthreads();
    for (int o = 128; o; o >>= 1) {
        if (t < o) sh[t] += sh[t + o];
        __syncthreads();
    }
    if (t == 0) g_part[blockIdx.x] = sh[0];
}

__global__ void k_scanpart() {   // 1 block: g_part <- INCLUSIVE scan of g_part
    __shared__ int sh[512];
    int t = threadIdx.x;
    sh[t] = (t < NB_NODE) ? g_part[t] : 0;
    __syncthreads();
    for (int o = 1; o < 512; o <<= 1) {
        int v = (t >= o) ? sh[t - o] : 0;
        __syncthreads();
        if (t >= o) sh[t] += v;
        __syncthreads();
    }
    if (t < NB_NODE) g_part[t] = sh[t];
}

__global__ void k_scanfinal() {
    __shared__ int sh[256];
    int t = threadIdx.x;
    int n = blockIdx.x * 256 + t;
    int v = (n < NN) ? g_cnt[n] : 0;
    sh[t] = v;
    __syncthreads();
    for (int o = 1; o < 256; o <<= 1) {
        int u = (t >= o) ? sh[t - o] : 0;
        __syncthreads();
        if (t >= o) sh[t] += u;
        __syncthreads();
    }
    if (n < NN) {
        int excl = sh[t] - v;
        int base = (blockIdx.x > 0) ? g_part[blockIdx.x - 1] : 0;
        int off = base + excl;
        g_off[n] = off;
        g_cur[n] = off;
    }
}

__global__ void k_scatter(const int* __restrict__ ei, const float* __restrict__ ew) {
    int e = blockIdx.x * blockDim.x + threadIdx.x;
    if (e >= NE) return;
    int s = ei[e];
    int d = ei[NE + e];
    float nw = g_dis[s] * ew[e] * g_dis[d];
    int pos = atomicAdd(&g_cur[d], 1);
    g_csrc[pos] = s;
    g_cw[pos]   = nw;
}

// ---------------------------------------------------------------------------
// Fused propagation step (atomic-free):
//   fout[n] = (1-a)*( fin[n]*dis[n]^2 + sum_j cw[j]*fin[csrc[j]] ) + a*f0[n]
// ---------------------------------------------------------------------------
__global__ void k_prop(const float* __restrict__ fin, float* __restrict__ fout,
                       const float* __restrict__ alpha_p) {
    int n = blockIdx.x * blockDim.x + threadIdx.x;
    if (n >= NN) return;
    float dis = g_dis[n];
    float acc = fin[n] * dis * dis;
    int beg = g_off[n];
    int end = beg + g_cnt[n];
    for (int j = beg; j < end; j++)
        acc = fmaf(g_cw[j], __ldg(&fin[g_csrc[j]]), acc);
    float a = *alpha_p;
    fout[n] = (1.0f - a) * acc + a * g_f0[n];
}

// ---------------------------------------------------------------------------
// Launch
// ---------------------------------------------------------------------------
extern "C" void kernel_launch(void* const* d_in, const int* in_sizes, int n_in,
                              void* d_out, int out_size) {
    const float* x = (const float*)d_in[0];
    const float* mask = (const float*)d_in[1];
    const int* ei = (const int*)d_in[2];
    const float* W = (const float*)d_in[3];
    const float* b = (const float*)d_in[4];
    const float* alpha = (const float*)d_in[5];
    float* out = (float*)d_out;              // [0, NN): f, [NN, NN+NE): edge_weights
    float* ew_out = out + NN;

    const int TB = 256;
    int edgeBlocks = (NE + TB - 1) / TB;

    k_feat<<<(NN + 7) / 8, 256>>>(x, W, b);
    k_init<<<NB_NODE, TB>>>(mask);
    k_edge<<<(NE * 16 + TB - 1) / TB, TB>>>(ei, ew_out);
    k_dis<<<NB_NODE, TB>>>();

    k_blocksum<<<NB_NODE, 256>>>();
    k_scanpart<<<1, 512>>>();
    k_scanfinal<<<NB_NODE, 256>>>();
    k_scatter<<<edgeBlocks, TB>>>(ei, ew_out);

    static float* p_f = nullptr;
    static float* p_f2 = nullptr;
    if (!p_f)  cudaGetSymbolAddress((void**)&p_f,  g_f);
    if (!p_f2) cudaGetSymbolAddress((void**)&p_f2, g_f2);

    const float* cur = p_f;
    float* nxt = p_f2;
    for (int it = 0; it < K_ITERS; it++) {
        float* dst = (it == K_ITERS - 1) ? out : nxt;
        k_prop<<<NB_NODE, TB>>>(cur, dst, alpha);
        const float* tmp = cur;
        cur = dst;
        nxt = (float*)tmp;
    }
}

// round 9
// speedup vs baseline: 7.7996x; 7.7996x over previous
#include <cuda_runtime.h>
#include <cuda_bf16.h>

#define NN 100000
#define NE 1250000
#define DD 64
#define K_ITERS 5
#define EPSF 1e-8f
#define NB_NODE 391            // ceil(NN/256)

// Scratch (device globals — allocation-free).
__device__ __align__(16) float g_hn[NN * DD]; // normalized tanh features
__device__ float g_deg[NN];     // weighted degree (incl. self loop)
__device__ float g_dis[NN];     // deg^{-1/2}
__device__ float g_f[NN];       // propagation ping
__device__ float g_f2[NN];      // propagation pong
__device__ float g_f0[NN];      // relu(mask)
// CSR by destination
__device__ int   g_cnt[NN];
__device__ int   g_off[NN];
__device__ int   g_cur[NN];
__device__ int   g_part[512];
__device__ int   g_csrc[NE];
__device__ float g_cw[NE];

// ---------------------------------------------------------------------------
// K1: h = tanh(x @ W^T + b), rows normalized: hn = h / max(||h||, eps)
// W staged TRANSPOSED in smem -> conflict-free LDS, coalesced everywhere.
// Block: 256 thr = 8 warps; each warp computes 4 rows; 32 rows/block.
// ---------------------------------------------------------------------------
__global__ void k_feat(const float* __restrict__ x, const float* __restrict__ W,
                       const float* __restrict__ b) {
    __shared__ float Wt[DD][DD + 1];   // Wt[k][j] = W[j][k], padded
    __shared__ float xs[32][DD];       // 32 rows of x
    __shared__ float bs[DD];

    int tid = threadIdx.x;
    int row0 = blockIdx.x * 32;

    // Load W transposed (coalesced GMEM read: consecutive tid -> consecutive i)
    for (int i = tid; i < DD * DD; i += 256) {
        int j = i >> 6, k = i & 63;
        Wt[k][j] = W[i];
    }
    if (tid < DD) bs[tid] = b[tid];
    // Load 32 x-rows (coalesced)
    for (int i = tid; i < 32 * DD; i += 256) {
        int r = i >> 6, k = i & 63;
        int n = row0 + r;
        xs[r][k] = (n < NN) ? x[n * DD + k] : 0.0f;
    }
    __syncthreads();

    int warp = tid >> 5, lane = tid & 31;
    int rbase = warp * 4;

    float acc[4][2];
#pragma unroll
    for (int r = 0; r < 4; r++) {
        acc[r][0] = bs[lane];
        acc[r][1] = bs[lane + 32];
    }

#pragma unroll 8
    for (int k = 0; k < DD; k++) {
        float w0 = Wt[k][lane];        // lanes consecutive -> conflict-free
        float w1 = Wt[k][lane + 32];
#pragma unroll
        for (int r = 0; r < 4; r++) {
            float xv = xs[rbase + r][k];  // broadcast
            acc[r][0] = fmaf(xv, w0, acc[r][0]);
            acc[r][1] = fmaf(xv, w1, acc[r][1]);
        }
    }

#pragma unroll
    for (int r = 0; r < 4; r++) {
        int n = row0 + rbase + r;
        if (n >= NN) break;
        float a0 = tanhf(acc[r][0]);
        float a1 = tanhf(acc[r][1]);
        float ss = a0 * a0 + a1 * a1;
#pragma unroll
        for (int o = 16; o; o >>= 1) ss += __shfl_xor_sync(0xffffffffu, ss, o);
        float inv = 1.0f / fmaxf(sqrtf(ss), EPSF);
        g_hn[n * DD + lane]      = a0 * inv;
        g_hn[n * DD + lane + 32] = a1 * inv;
    }
}

// ---------------------------------------------------------------------------
__global__ void k_init(const float* __restrict__ mask) {
    int n = blockIdx.x * blockDim.x + threadIdx.x;
    if (n < NN) {
        g_deg[n] = 1.0f;
        g_cnt[n] = 0;
        float f0 = fmaxf(mask[n], 0.0f);
        g_f0[n] = f0;
        g_f[n]  = f0;
    }
}

// ---------------------------------------------------------------------------
// K2: edge cosine (relu), weighted-degree + in-degree-count accumulation.
// ---------------------------------------------------------------------------
__global__ void k_edge(const int* __restrict__ ei, float* __restrict__ ew_out) {
    int t = blockIdx.x * blockDim.x + threadIdx.x;
    int e = t >> 4;
    int sub = t & 15;
    if (e >= NE) return;

    int s = ei[e];
    int d = ei[NE + e];

    float4 a = *(const float4*)(g_hn + s * DD + sub * 4);
    float4 c = *(const float4*)(g_hn + d * DD + sub * 4);
    float p = a.x * c.x + a.y * c.y + a.z * c.z + a.w * c.w;
#pragma unroll
    for (int o = 8; o; o >>= 1) p += __shfl_xor_sync(0xffffffffu, p, o);

    if (sub == 0) {
        float w = fmaxf(p, 0.0f);
        ew_out[e] = w;
        atomicAdd(&g_deg[d], w);
        atomicAdd(&g_cnt[d], 1);
    }
}

// ---------------------------------------------------------------------------
__global__ void k_dis() {
    int n = blockIdx.x * blockDim.x + threadIdx.x;
    if (n < NN) g_dis[n] = rsqrtf(fmaxf(g_deg[n], EPSF));
}

// ---------------------------------------------------------------------------
// CSR build: block sums -> inclusive scan of partials -> local scan + base.
// ---------------------------------------------------------------------------
__global__ void k_blocksum() {
    __shared__ int sh[256];
    int t = threadIdx.x;
    int n = blockIdx.x * 256 + t;
    sh[t] = (n < NN) ? g_cnt[n] : 0;
    __syncthreads();
    for (int o = 128; o; o >>= 1) {
        if (t < o) sh[t] += sh[t + o];
        __syncthreads();
    }
    if (t == 0) g_part[blockIdx.x] = sh[0];
}

__global__ void k_scanpart() {   // 1 block: g_part <- INCLUSIVE scan
    __shared__ int sh[512];
    int t = threadIdx.x;
    sh[t] = (t < NB_NODE) ? g_part[t] : 0;
    __syncthreads();
    for (int o = 1; o < 512; o <<= 1) {
        int v = (t >= o) ? sh[t - o] : 0;
        __syncthreads();
        if (t >= o) sh[t] += v;
        __syncthreads();
    }
    if (t < NB_NODE) g_part[t] = sh[t];
}

__global__ void k_scanfinal() {
    __shared__ int sh[256];
    int t = threadIdx.x;
    int n = blockIdx.x * 256 + t;
    int v = (n < NN) ? g_cnt[n] : 0;
    sh[t] = v;
    __syncthreads();
    for (int o = 1; o < 256; o <<= 1) {
        int u = (t >= o) ? sh[t - o] : 0;
        __syncthreads();
        if (t >= o) sh[t] += u;
        __syncthreads();
    }
    if (n < NN) {
        int off = ((blockIdx.x > 0) ? g_part[blockIdx.x - 1] : 0) + sh[t] - v;
        g_off[n] = off;
        g_cur[n] = off;
    }
}

__global__ void k_scatter(const int* __restrict__ ei, const float* __restrict__ ew) {
    int e = blockIdx.x * blockDim.x + threadIdx.x;
    if (e >= NE) return;
    int s = ei[e];
    int d = ei[NE + e];
    float nw = g_dis[s] * ew[e] * g_dis[d];
    int pos = atomicAdd(&g_cur[d], 1);
    g_csrc[pos] = s;
    g_cw[pos]   = nw;
}

// ---------------------------------------------------------------------------
// Fused propagation step (atomic-free).
// ---------------------------------------------------------------------------
__global__ void k_prop(const float* __restrict__ fin, float* __restrict__ fout,
                       const float* __restrict__ alpha_p) {
    int n = blockIdx.x * blockDim.x + threadIdx.x;
    if (n >= NN) return;
    float dis = g_dis[n];
    float acc = fin[n] * dis * dis;
    int beg = g_off[n];
    int end = beg + g_cnt[n];
    for (int j = beg; j < end; j++)
        acc = fmaf(g_cw[j], __ldg(&fin[g_csrc[j]]), acc);
    float a = *alpha_p;
    fout[n] = (1.0f - a) * acc + a * g_f0[n];
}

// ---------------------------------------------------------------------------
extern "C" void kernel_launch(void* const* d_in, const int* in_sizes, int n_in,
                              void* d_out, int out_size) {
    const float* x = (const float*)d_in[0];
    const float* mask = (const float*)d_in[1];
    const int* ei = (const int*)d_in[2];
    const float* W = (const float*)d_in[3];
    const float* b = (const float*)d_in[4];
    const float* alpha = (const float*)d_in[5];
    float* out = (float*)d_out;              // [0, NN): f, [NN, NN+NE): edge_weights
    float* ew_out = out + NN;

    const int TB = 256;
    int edgeBlocks = (NE + TB - 1) / TB;

    k_feat<<<(NN + 31) / 32, 256>>>(x, W, b);
    k_init<<<NB_NODE, TB>>>(mask);
    k_edge<<<(NE * 16 + TB - 1) / TB, TB>>>(ei, ew_out);
    k_dis<<<NB_NODE, TB>>>();

    k_blocksum<<<NB_NODE, 256>>>();
    k_scanpart<<<1, 512>>>();
    k_scanfinal<<<NB_NODE, 256>>>();
    k_scatter<<<edgeBlocks, TB>>>(ei, ew_out);

    static float* p_f = nullptr;
    static float* p_f2 = nullptr;
    if (!p_f)  cudaGetSymbolAddress((void**)&p_f,  g_f);
    if (!p_f2) cudaGetSymbolAddress((void**)&p_f2, g_f2);

    const float* cur = p_f;
    float* nxt = p_f2;
    for (int it = 0; it < K_ITERS; it++) {
        float* dst = (it == K_ITERS - 1) ? out : nxt;
        k_prop<<<NB_NODE, TB>>>(cur, dst, alpha);
        const float* tmp = cur;
        cur = dst;
        nxt = (float*)tmp;
    }
}